// round 1
// baseline (speedup 1.0000x reference)
#include <cuda_runtime.h>
#include <math.h>

#define BB   16
#define LL   1024
#define DD   384
#define FF   1536
#define TOUT 10240
#define MAXDUR 10

// Scratch (device globals: allocation-free rule)
__device__ float g_h1a[BB*LL*FF];   // conv1a out (relu)
__device__ float g_h1b[BB*LL*DD];   // conv1b out (relu, pre-LN)
__device__ float g_h1n[BB*LL*DD];   // after LN1
__device__ float g_h2a[BB*LL*FF];   // conv2a out
__device__ float g_h2b[BB*LL*DD];   // conv2b out (pre-LN2)
__device__ int   g_lns[BB*LL];
__device__ int   g_csum[BB*LL];
__device__ int   g_tot[BB];

// ---------------------------------------------------------------------------
// Conv1d (K=3, SAME) + bias + ReLU.  out[b,l,co] = relu(sum_{k,ci} in[b,l+k-1,ci]*w[co,ci,k]+bias[co])
// Tile: 64 l-rows x 64 co-cols per block, 256 threads, 4x4 microtile.
// Rows beyond min(L, tlen[b]+margin) are skipped at block granularity (their
// values are never consumed downstream by construction of the margins).
// ---------------------------------------------------------------------------
template<int CIN, int COUT>
__global__ __launch_bounds__(256)
void conv_relu_kernel(const float* __restrict__ in, const float* __restrict__ w,
                      const float* __restrict__ bias, float* __restrict__ out,
                      const int* __restrict__ tlen, int margin)
{
    const int b     = blockIdx.z;
    const int lbase = blockIdx.x * 64;
    const int cbase = blockIdx.y * 64;
    int limit = tlen[b] + margin; if (limit > LL) limit = LL;
    if (lbase >= limit) return;

    __shared__ float As[16][67];      // [ci][l_local], l_local in [0,65] -> global l = lbase-1+l_local
    __shared__ float Ws[16][3][65];   // [ci][k][co] padded for bank-conflict-free access

    const int tid = threadIdx.x;
    const int tx  = tid & 15;         // col group
    const int ty  = tid >> 4;         // row group (4 contiguous rows)

    float acc[4][4];
#pragma unroll
    for (int i = 0; i < 4; i++)
#pragma unroll
        for (int j = 0; j < 4; j++) acc[i][j] = 0.f;

    const float* inB = in + (size_t)b * LL * CIN;

    for (int cb = 0; cb < CIN; cb += 16) {
        // A tile: 16 ci x 66 rows (with zero padding at sequence ends)
        for (int i = tid; i < 16*66; i += 256) {
            int ci = i & 15, ll = i >> 4;
            int gl = lbase + ll - 1;
            float v = 0.f;
            if (gl >= 0 && gl < LL) v = inB[(size_t)gl * CIN + cb + ci];
            As[ci][ll] = v;
        }
        // W tile: 64 co x 16 ci x 3 k
        for (int i = tid; i < 16*3*64; i += 256) {
            int co = i / 48; int r = i - co * 48; int ci = r / 3; int k = r - ci * 3;
            Ws[ci][k][co] = w[((size_t)(cbase + co) * CIN + cb + ci) * 3 + k];
        }
        __syncthreads();

#pragma unroll
        for (int ci = 0; ci < 16; ci++) {
            float a[6];
#pragma unroll
            for (int i = 0; i < 6; i++) a[i] = As[ci][ty * 4 + i];
            float wv[3][4];
#pragma unroll
            for (int k = 0; k < 3; k++)
#pragma unroll
                for (int j = 0; j < 4; j++) wv[k][j] = Ws[ci][k][tx + 16 * j];
#pragma unroll
            for (int i = 0; i < 4; i++)
#pragma unroll
                for (int j = 0; j < 4; j++)
                    acc[i][j] += a[i] * wv[0][j] + a[i+1] * wv[1][j] + a[i+2] * wv[2][j];
        }
        __syncthreads();
    }

#pragma unroll
    for (int j = 0; j < 4; j++) {
        int co = cbase + tx + 16 * j;
        float bv = bias[co];
#pragma unroll
        for (int i = 0; i < 4; i++) {
            int l = lbase + ty * 4 + i;
            out[((size_t)b * LL + l) * COUT + co] = fmaxf(acc[i][j] + bv, 0.f);
        }
    }
}

// ---------------------------------------------------------------------------
// LayerNorm over D=384, one warp per (b,l) row. Two-pass mean/var.
// ---------------------------------------------------------------------------
__global__ __launch_bounds__(256)
void ln_kernel(const float* __restrict__ in, const float* __restrict__ g,
               const float* __restrict__ be, float* __restrict__ out,
               const int* __restrict__ tlen, int margin)
{
    int b = blockIdx.y;
    int l = blockIdx.x * 8 + (threadIdx.x >> 5);
    int lane = threadIdx.x & 31;
    int limit = tlen[b] + margin; if (limit > LL) limit = LL;
    if (l >= limit) return;

    size_t base = ((size_t)b * LL + l) * DD;
    float x[12];
#pragma unroll
    for (int i = 0; i < 12; i++) x[i] = in[base + lane + 32 * i];
    float s = 0.f;
#pragma unroll
    for (int i = 0; i < 12; i++) s += x[i];
#pragma unroll
    for (int o = 16; o > 0; o >>= 1) s += __shfl_xor_sync(0xffffffffu, s, o);
    float mu = s * (1.f / DD);
    float q = 0.f;
#pragma unroll
    for (int i = 0; i < 12; i++) { float d = x[i] - mu; q += d * d; }
#pragma unroll
    for (int o = 16; o > 0; o >>= 1) q += __shfl_xor_sync(0xffffffffu, q, o);
    float rstd = 1.f / sqrtf(q * (1.f / DD) + 1e-5f);
#pragma unroll
    for (int i = 0; i < 12; i++) {
        int d = lane + 32 * i;
        out[base + d] = (x[i] - mu) * rstd * g[d] + be[d];
    }
}

// ---------------------------------------------------------------------------
// Fused LN2 + linear (D->1) + durations. One warp per (b,l).
// lns = clip(round(exp(pred)), 0, 10), masked by token length.
// ---------------------------------------------------------------------------
__global__ __launch_bounds__(256)
void pred_kernel(const float* __restrict__ in, const float* __restrict__ g,
                 const float* __restrict__ be, const float* __restrict__ wl,
                 const float* __restrict__ bl, const int* __restrict__ tlen,
                 int* __restrict__ lns)
{
    int b = blockIdx.y;
    int l = blockIdx.x * 8 + (threadIdx.x >> 5);
    int lane = threadIdx.x & 31;
    if (l >= tlen[b]) { if (lane == 0) lns[b * LL + l] = 0; return; }

    size_t base = ((size_t)b * LL + l) * DD;
    float x[12];
#pragma unroll
    for (int i = 0; i < 12; i++) x[i] = in[base + lane + 32 * i];
    float s = 0.f;
#pragma unroll
    for (int i = 0; i < 12; i++) s += x[i];
#pragma unroll
    for (int o = 16; o > 0; o >>= 1) s += __shfl_xor_sync(0xffffffffu, s, o);
    float mu = s * (1.f / DD);
    float q = 0.f;
#pragma unroll
    for (int i = 0; i < 12; i++) { float d = x[i] - mu; q += d * d; }
#pragma unroll
    for (int o = 16; o > 0; o >>= 1) q += __shfl_xor_sync(0xffffffffu, q, o);
    float rstd = 1.f / sqrtf(q * (1.f / DD) + 1e-5f);
    float p = 0.f;
#pragma unroll
    for (int i = 0; i < 12; i++) {
        int d = lane + 32 * i;
        p += ((x[i] - mu) * rstd * g[d] + be[d]) * wl[d];
    }
#pragma unroll
    for (int o = 16; o > 0; o >>= 1) p += __shfl_xor_sync(0xffffffffu, p, o);
    if (lane == 0) {
        float e = expf(p + bl[0]);
        float r = rintf(e);                // round-half-even matches jnp.round
        if (r > (float)MAXDUR) r = (float)MAXDUR;
        lns[b * LL + l] = (int)r;
    }
}

// ---------------------------------------------------------------------------
// Inclusive scan of durations per batch row (L=1024, one block per row).
// Also writes totals (and the totals tail of d_out as float).
// ---------------------------------------------------------------------------
__global__ __launch_bounds__(1024)
void scan_kernel(const int* __restrict__ lns, int* __restrict__ csum,
                 int* __restrict__ tot, float* __restrict__ out_tail, int write_tail)
{
    __shared__ int s[1024];
    int b = blockIdx.x, t = threadIdx.x;
    s[t] = lns[b * LL + t];
    __syncthreads();
    for (int o = 1; o < 1024; o <<= 1) {
        int v = (t >= o) ? s[t - o] : 0;
        __syncthreads();
        s[t] += v;
        __syncthreads();
    }
    csum[b * LL + t] = s[t];
    if (t == 1023) {
        tot[b] = s[t];
        if (write_tail) out_tail[b] = (float)s[t];
    }
}

// ---------------------------------------------------------------------------
// Expansion gather: one warp per output timestep t; binary search csum,
// copy y[b, idx, :] (or zeros past totals). 252 MB of writes, float4.
// ---------------------------------------------------------------------------
__global__ __launch_bounds__(256)
void gather_kernel(const float* __restrict__ y, const int* __restrict__ csum,
                   const int* __restrict__ tot, float* __restrict__ out)
{
    int b = blockIdx.y;
    int t = blockIdx.x * 8 + (threadIdx.x >> 5);
    int lane = threadIdx.x & 31;

    int idx = 0;
    if (lane == 0) {
        const int* c = csum + b * LL;
        int lo = 0, hi = LL;                 // upper_bound: first i with c[i] > t
        while (lo < hi) { int mid = (lo + hi) >> 1; if (c[mid] <= t) lo = mid + 1; else hi = mid; }
        idx = (lo < LL - 1) ? lo : (LL - 1);
    }
    idx = __shfl_sync(0xffffffffu, idx, 0);
    bool valid = t < tot[b];

    const float4* src = (const float4*)(y + ((size_t)b * LL + idx) * DD);
    float4*       dst = (float4*)(out + ((size_t)b * TOUT + t) * DD);
    float4 z = make_float4(0.f, 0.f, 0.f, 0.f);
#pragma unroll
    for (int i = 0; i < 3; i++) dst[lane + 32 * i] = valid ? src[lane + 32 * i] : z;
}

// ---------------------------------------------------------------------------
extern "C" void kernel_launch(void* const* d_in, const int* in_sizes, int n_in,
                              void* d_out, int out_size)
{
    const float* y    = (const float*)d_in[0];
    const int*   tlen = (const int*)  d_in[1];
    const float* w1a  = (const float*)d_in[2];
    const float* b1a  = (const float*)d_in[3];
    const float* w1b  = (const float*)d_in[4];
    const float* b1b  = (const float*)d_in[5];
    const float* g1   = (const float*)d_in[6];
    const float* be1  = (const float*)d_in[7];
    const float* w2a  = (const float*)d_in[8];
    const float* b2a  = (const float*)d_in[9];
    const float* w2b  = (const float*)d_in[10];
    const float* b2b  = (const float*)d_in[11];
    const float* g2   = (const float*)d_in[12];
    const float* be2  = (const float*)d_in[13];
    const float* wl   = (const float*)d_in[14];
    const float* bl   = (const float*)d_in[15];
    float* out = (float*)d_out;

    float *h1a, *h1b, *h1n, *h2a, *h2b; int *lns, *csum, *tot;
    cudaGetSymbolAddress((void**)&h1a, g_h1a);
    cudaGetSymbolAddress((void**)&h1b, g_h1b);
    cudaGetSymbolAddress((void**)&h1n, g_h1n);
    cudaGetSymbolAddress((void**)&h2a, g_h2a);
    cudaGetSymbolAddress((void**)&h2b, g_h2b);
    cudaGetSymbolAddress((void**)&lns, g_lns);
    cudaGetSymbolAddress((void**)&csum, g_csum);
    cudaGetSymbolAddress((void**)&tot, g_tot);

    dim3 gA(LL / 64, FF / 64, BB);   // D -> F convs
    dim3 gB(LL / 64, DD / 64, BB);   // F -> D convs
    dim3 gR(LL / 8, BB);             // per-row kernels

    conv_relu_kernel<DD, FF><<<gA, 256>>>(y,   w1a, b1a, h1a, tlen, 3);
    conv_relu_kernel<FF, DD><<<gB, 256>>>(h1a, w1b, b1b, h1b, tlen, 2);
    ln_kernel<<<gR, 256>>>(h1b, g1, be1, h1n, tlen, 2);
    conv_relu_kernel<DD, FF><<<gA, 256>>>(h1n, w2a, b2a, h2a, tlen, 1);
    conv_relu_kernel<FF, DD><<<gB, 256>>>(h2a, w2b, b2b, h2b, tlen, 0);
    pred_kernel<<<gR, 256>>>(h2b, g2, be2, wl, bl, tlen, lns);

    int write_tail = (out_size >= BB * TOUT * DD + BB) ? 1 : 0;
    scan_kernel<<<BB, 1024>>>(lns, csum, tot, out + (size_t)BB * TOUT * DD, write_tail);
    gather_kernel<<<dim3(TOUT / 8, BB), 256>>>(y, csum, tot, out);
}

// round 2
// speedup vs baseline: 1.9082x; 1.9082x over previous
#include <cuda_runtime.h>
#include <math.h>

#define BB   16
#define LL   1024
#define DD   384
#define FF   1536
#define TOUT 10240
#define MAXDUR 10

// Scratch (device globals: allocation-free rule)
__device__ float g_h1a[BB*LL*FF];   // conv1a out (relu)
__device__ float g_h1b[BB*LL*DD];   // conv1b out (relu, pre-LN)
__device__ float g_h1n[BB*LL*DD];   // after LN1
__device__ float g_h2a[BB*LL*FF];   // conv2a out
__device__ float g_h2b[BB*LL*DD];   // conv2b out (pre-LN2)
__device__ int   g_lns[BB*LL];
__device__ int   g_csum[BB*LL];
__device__ int   g_tot[BB];
// Transposed weights: wT[ci][k][co]
__device__ float g_w1aT[DD*3*FF];
__device__ float g_w1bT[FF*3*DD];
__device__ float g_w2aT[DD*3*FF];
__device__ float g_w2bT[FF*3*DD];

// ---------------------------------------------------------------------------
// Weight transpose: w[co][ci][k] -> wT[ci][k][co].
// One block per co; threads read the contiguous (ci,k) run for that co
// (coalesced within the run), write strided (absorbed by L2 write-back).
// ---------------------------------------------------------------------------
__global__ __launch_bounds__(256)
void wtr_kernel(const float* __restrict__ w, float* __restrict__ wT,
                int cin, int cout)
{
    int co = blockIdx.x;
    const float* src = w + (size_t)co * cin * 3;
    for (int r = threadIdx.x; r < cin * 3; r += 256)
        wT[(size_t)r * cout + co] = src[r];
}

// ---------------------------------------------------------------------------
// Conv1d (K=3, SAME) + bias + ReLU, GEMM-style.
// Block tile: 128 l-rows x 64 co-cols, 256 threads, 8x4 microtile.
// Weights pre-transposed to wT[ci][k][co].
// ---------------------------------------------------------------------------
template<int CIN, int COUT>
__global__ __launch_bounds__(256)
void conv_relu_kernel(const float* __restrict__ in, const float* __restrict__ wT,
                      const float* __restrict__ bias, float* __restrict__ out,
                      const int* __restrict__ tlen, int margin)
{
    const int b     = blockIdx.z;
    const int lbase = blockIdx.x * 128;
    const int cbase = blockIdx.y * 64;
    int limit = tlen[b] + margin; if (limit > LL) limit = LL;
    if (lbase >= limit) return;

    __shared__ float As[16][132];    // [ci][ll], ll in [0,129] -> l = lbase-1+ll
    __shared__ float Ws[16][3][64];  // [ci][k][co], 256B rows -> aligned float4

    const int tid = threadIdx.x;
    const int tx  = tid & 15;        // co group: owns co = cbase + tx*4 .. +3
    const int ty  = tid >> 4;        // row group: owns l = lbase + ty*8 .. +7

    float acc[8][4];
#pragma unroll
    for (int i = 0; i < 8; i++)
#pragma unroll
        for (int j = 0; j < 4; j++) acc[i][j] = 0.f;

    const float* inB = in + (size_t)b * LL * CIN;

    for (int cb = 0; cb < CIN; cb += 16) {
        // ---- A tile: 130 rows x 16 ci, loaded as float4 over ci ----
        // 130*4 = 520 float4 elements, ~2 per thread.
#pragma unroll 2
        for (int i = tid; i < 520; i += 256) {
            int ll = i >> 2, c4 = (i & 3) * 4;
            int gl = lbase + ll - 1;
            float4 v = make_float4(0.f, 0.f, 0.f, 0.f);
            if (gl >= 0 && gl < LL)
                v = *(const float4*)&inB[(size_t)gl * CIN + cb + c4];
            As[c4 + 0][ll] = v.x; As[c4 + 1][ll] = v.y;
            As[c4 + 2][ll] = v.z; As[c4 + 3][ll] = v.w;
        }
        // ---- W tile: wT[cb..cb+15][k][cbase..cbase+63], float4 both sides ----
        // 16*3*64 = 3072 floats = 768 float4, 3 per thread.
#pragma unroll
        for (int i = tid; i < 768; i += 256) {
            int r = i >> 4;          // r = ci*3 + k  (0..47)
            int c4 = (i & 15) * 4;   // co offset in tile
            float4 v = *(const float4*)&wT[((size_t)(cb * 3 + r)) * COUT + cbase + c4];
            *(float4*)&Ws[0][0][(size_t)r * 64 + c4] = v;
        }
        __syncthreads();

#pragma unroll
        for (int ci = 0; ci < 16; ci++) {
            float4 a03 = *(const float4*)&As[ci][ty * 8];
            float4 a47 = *(const float4*)&As[ci][ty * 8 + 4];
            float2 a89 = *(const float2*)&As[ci][ty * 8 + 8];
            float a[10] = {a03.x, a03.y, a03.z, a03.w,
                           a47.x, a47.y, a47.z, a47.w,
                           a89.x, a89.y};
            float4 w0 = *(const float4*)&Ws[ci][0][tx * 4];
            float4 w1 = *(const float4*)&Ws[ci][1][tx * 4];
            float4 w2 = *(const float4*)&Ws[ci][2][tx * 4];
            float wv0[4] = {w0.x, w0.y, w0.z, w0.w};
            float wv1[4] = {w1.x, w1.y, w1.z, w1.w};
            float wv2[4] = {w2.x, w2.y, w2.z, w2.w};
#pragma unroll
            for (int i = 0; i < 8; i++)
#pragma unroll
                for (int j = 0; j < 4; j++) {
                    acc[i][j] = fmaf(a[i],     wv0[j], acc[i][j]);
                    acc[i][j] = fmaf(a[i + 1], wv1[j], acc[i][j]);
                    acc[i][j] = fmaf(a[i + 2], wv2[j], acc[i][j]);
                }
        }
        __syncthreads();
    }

    const float4 bv = *(const float4*)&bias[cbase + tx * 4];
#pragma unroll
    for (int i = 0; i < 8; i++) {
        int l = lbase + ty * 8 + i;
        float4 o;
        o.x = fmaxf(acc[i][0] + bv.x, 0.f);
        o.y = fmaxf(acc[i][1] + bv.y, 0.f);
        o.z = fmaxf(acc[i][2] + bv.z, 0.f);
        o.w = fmaxf(acc[i][3] + bv.w, 0.f);
        *(float4*)&out[((size_t)b * LL + l) * COUT + cbase + tx * 4] = o;
    }
}

// ---------------------------------------------------------------------------
// LayerNorm over D=384, one warp per (b,l) row.
// ---------------------------------------------------------------------------
__global__ __launch_bounds__(256)
void ln_kernel(const float* __restrict__ in, const float* __restrict__ g,
               const float* __restrict__ be, float* __restrict__ out,
               const int* __restrict__ tlen, int margin)
{
    int b = blockIdx.y;
    int l = blockIdx.x * 8 + (threadIdx.x >> 5);
    int lane = threadIdx.x & 31;
    int limit = tlen[b] + margin; if (limit > LL) limit = LL;
    if (l >= limit) return;

    size_t base = ((size_t)b * LL + l) * DD;
    float x[12];
#pragma unroll
    for (int i = 0; i < 12; i++) x[i] = in[base + lane + 32 * i];
    float s = 0.f;
#pragma unroll
    for (int i = 0; i < 12; i++) s += x[i];
#pragma unroll
    for (int o = 16; o > 0; o >>= 1) s += __shfl_xor_sync(0xffffffffu, s, o);
    float mu = s * (1.f / DD);
    float q = 0.f;
#pragma unroll
    for (int i = 0; i < 12; i++) { float d = x[i] - mu; q += d * d; }
#pragma unroll
    for (int o = 16; o > 0; o >>= 1) q += __shfl_xor_sync(0xffffffffu, q, o);
    float rstd = 1.f / sqrtf(q * (1.f / DD) + 1e-5f);
#pragma unroll
    for (int i = 0; i < 12; i++) {
        int d = lane + 32 * i;
        out[base + d] = (x[i] - mu) * rstd * g[d] + be[d];
    }
}

// ---------------------------------------------------------------------------
// Fused LN2 + linear (D->1) + durations.
// ---------------------------------------------------------------------------
__global__ __launch_bounds__(256)
void pred_kernel(const float* __restrict__ in, const float* __restrict__ g,
                 const float* __restrict__ be, const float* __restrict__ wl,
                 const float* __restrict__ bl, const int* __restrict__ tlen,
                 int* __restrict__ lns)
{
    int b = blockIdx.y;
    int l = blockIdx.x * 8 + (threadIdx.x >> 5);
    int lane = threadIdx.x & 31;
    if (l >= tlen[b]) { if (lane == 0) lns[b * LL + l] = 0; return; }

    size_t base = ((size_t)b * LL + l) * DD;
    float x[12];
#pragma unroll
    for (int i = 0; i < 12; i++) x[i] = in[base + lane + 32 * i];
    float s = 0.f;
#pragma unroll
    for (int i = 0; i < 12; i++) s += x[i];
#pragma unroll
    for (int o = 16; o > 0; o >>= 1) s += __shfl_xor_sync(0xffffffffu, s, o);
    float mu = s * (1.f / DD);
    float q = 0.f;
#pragma unroll
    for (int i = 0; i < 12; i++) { float d = x[i] - mu; q += d * d; }
#pragma unroll
    for (int o = 16; o > 0; o >>= 1) q += __shfl_xor_sync(0xffffffffu, q, o);
    float rstd = 1.f / sqrtf(q * (1.f / DD) + 1e-5f);
    float p = 0.f;
#pragma unroll
    for (int i = 0; i < 12; i++) {
        int d = lane + 32 * i;
        p += ((x[i] - mu) * rstd * g[d] + be[d]) * wl[d];
    }
#pragma unroll
    for (int o = 16; o > 0; o >>= 1) p += __shfl_xor_sync(0xffffffffu, p, o);
    if (lane == 0) {
        float e = expf(p + bl[0]);
        float r = rintf(e);
        if (r > (float)MAXDUR) r = (float)MAXDUR;
        lns[b * LL + l] = (int)r;
    }
}

// ---------------------------------------------------------------------------
// Inclusive scan of durations per batch row.
// ---------------------------------------------------------------------------
__global__ __launch_bounds__(1024)
void scan_kernel(const int* __restrict__ lns, int* __restrict__ csum,
                 int* __restrict__ tot, float* __restrict__ out_tail, int write_tail)
{
    __shared__ int s[1024];
    int b = blockIdx.x, t = threadIdx.x;
    s[t] = lns[b * LL + t];
    __syncthreads();
    for (int o = 1; o < 1024; o <<= 1) {
        int v = (t >= o) ? s[t - o] : 0;
        __syncthreads();
        s[t] += v;
        __syncthreads();
    }
    csum[b * LL + t] = s[t];
    if (t == 1023) {
        tot[b] = s[t];
        if (write_tail) out_tail[b] = (float)s[t];
    }
}

// ---------------------------------------------------------------------------
// Expansion gather.
// ---------------------------------------------------------------------------
__global__ __launch_bounds__(256)
void gather_kernel(const float* __restrict__ y, const int* __restrict__ csum,
                   const int* __restrict__ tot, float* __restrict__ out)
{
    int b = blockIdx.y;
    int t = blockIdx.x * 8 + (threadIdx.x >> 5);
    int lane = threadIdx.x & 31;

    int idx = 0;
    if (lane == 0) {
        const int* c = csum + b * LL;
        int lo = 0, hi = LL;
        while (lo < hi) { int mid = (lo + hi) >> 1; if (c[mid] <= t) lo = mid + 1; else hi = mid; }
        idx = (lo < LL - 1) ? lo : (LL - 1);
    }
    idx = __shfl_sync(0xffffffffu, idx, 0);
    bool valid = t < tot[b];

    const float4* src = (const float4*)(y + ((size_t)b * LL + idx) * DD);
    float4*       dst = (float4*)(out + ((size_t)b * TOUT + t) * DD);
    float4 z = make_float4(0.f, 0.f, 0.f, 0.f);
#pragma unroll
    for (int i = 0; i < 3; i++) dst[lane + 32 * i] = valid ? src[lane + 32 * i] : z;
}

// ---------------------------------------------------------------------------
extern "C" void kernel_launch(void* const* d_in, const int* in_sizes, int n_in,
                              void* d_out, int out_size)
{
    const float* y    = (const float*)d_in[0];
    const int*   tlen = (const int*)  d_in[1];
    const float* w1a  = (const float*)d_in[2];
    const float* b1a  = (const float*)d_in[3];
    const float* w1b  = (const float*)d_in[4];
    const float* b1b  = (const float*)d_in[5];
    const float* g1   = (const float*)d_in[6];
    const float* be1  = (const float*)d_in[7];
    const float* w2a  = (const float*)d_in[8];
    const float* b2a  = (const float*)d_in[9];
    const float* w2b  = (const float*)d_in[10];
    const float* b2b  = (const float*)d_in[11];
    const float* g2   = (const float*)d_in[12];
    const float* be2  = (const float*)d_in[13];
    const float* wl   = (const float*)d_in[14];
    const float* bl   = (const float*)d_in[15];
    float* out = (float*)d_out;

    float *h1a, *h1b, *h1n, *h2a, *h2b; int *lns, *csum, *tot;
    float *w1aT, *w1bT, *w2aT, *w2bT;
    cudaGetSymbolAddress((void**)&h1a, g_h1a);
    cudaGetSymbolAddress((void**)&h1b, g_h1b);
    cudaGetSymbolAddress((void**)&h1n, g_h1n);
    cudaGetSymbolAddress((void**)&h2a, g_h2a);
    cudaGetSymbolAddress((void**)&h2b, g_h2b);
    cudaGetSymbolAddress((void**)&lns, g_lns);
    cudaGetSymbolAddress((void**)&csum, g_csum);
    cudaGetSymbolAddress((void**)&tot, g_tot);
    cudaGetSymbolAddress((void**)&w1aT, g_w1aT);
    cudaGetSymbolAddress((void**)&w1bT, g_w1bT);
    cudaGetSymbolAddress((void**)&w2aT, g_w2aT);
    cudaGetSymbolAddress((void**)&w2bT, g_w2bT);

    // Weight transposes (run every launch; ~tens of microseconds)
    wtr_kernel<<<FF, 256>>>(w1a, w1aT, DD, FF);
    wtr_kernel<<<DD, 256>>>(w1b, w1bT, FF, DD);
    wtr_kernel<<<FF, 256>>>(w2a, w2aT, DD, FF);
    wtr_kernel<<<DD, 256>>>(w2b, w2bT, FF, DD);

    dim3 gA(LL / 128, FF / 64, BB);  // D -> F convs
    dim3 gB(LL / 128, DD / 64, BB);  // F -> D convs
    dim3 gR(LL / 8, BB);             // per-row kernels

    conv_relu_kernel<DD, FF><<<gA, 256>>>(y,   w1aT, b1a, h1a, tlen, 3);
    conv_relu_kernel<FF, DD><<<gB, 256>>>(h1a, w1bT, b1b, h1b, tlen, 2);
    ln_kernel<<<gR, 256>>>(h1b, g1, be1, h1n, tlen, 2);
    conv_relu_kernel<DD, FF><<<gA, 256>>>(h1n, w2aT, b2a, h2a, tlen, 1);
    conv_relu_kernel<FF, DD><<<gB, 256>>>(h2a, w2bT, b2b, h2b, tlen, 0);
    pred_kernel<<<gR, 256>>>(h2b, g2, be2, wl, bl, tlen, lns);

    int write_tail = (out_size >= BB * TOUT * DD + BB) ? 1 : 0;
    scan_kernel<<<BB, 1024>>>(lns, csum, tot, out + (size_t)BB * TOUT * DD, write_tail);
    gather_kernel<<<dim3(TOUT / 8, BB), 256>>>(y, csum, tot, out);
}